// round 8
// baseline (speedup 1.0000x reference)
#include <cuda_runtime.h>
#include <math.h>
#include <cstdint>

// Problem constants
#define NB    16
#define NPTS  4096
#define MPTS  1024
#define CH2   256
#define CH1   128
#define OUT1  256
#define OUT2  256
#define LDA_W1 384

// ---- scratch ----
__device__ int   g_idx[NB * NPTS * 3];
__device__ float g_wgt[NB * NPTS * 3];
__device__ float g_Tt [NB * MPTS * OUT1];    // T transposed: [b][m][o], fp32
__device__ float g_y1 [NB * OUT1 * NPTS];    // layer-1 activations, TF32 BIT PATTERNS
__device__ float g_W1c[OUT1 * LDA_W1];       // W1 pre-converted to tf32 bits
__device__ float g_W2c[OUT2 * OUT1];         // W2 pre-converted to tf32 bits

// ===========================================================================
__device__ __forceinline__ uint32_t f2tf32(float x) {
    uint32_t r;
    asm("cvt.rna.tf32.f32 %0, %1;" : "=r"(r) : "f"(x));
    return r;
}
__device__ __forceinline__ uint32_t smem_u32(const void* p) {
    uint32_t a;
    asm("{ .reg .u64 t; cvta.to.shared.u64 t, %1; cvt.u32.u64 %0, t; }" : "=r"(a) : "l"(p));
    return a;
}
__device__ __forceinline__ void cp16(void* dst, const void* src) {
    asm volatile("cp.async.ca.shared.global [%0], [%1], 16;"
                 :: "r"(smem_u32(dst)), "l"(src));
}

// ===========================================================================
// Kernel 0: pre-convert W1, W2 to tf32 bit patterns (one-shot, tiny)
// ===========================================================================
__global__ __launch_bounds__(256)
void conv_w_kernel(const float* __restrict__ W1, const float* __restrict__ W2)
{
    int i = blockIdx.x * blockDim.x + threadIdx.x;
    if (i < OUT1 * LDA_W1)
        g_W1c[i] = __uint_as_float(f2tf32(W1[i]));
    if (i < OUT2 * OUT1)
        g_W2c[i] = __uint_as_float(f2tf32(W2[i]));
}

// ===========================================================================
// Kernel 1: three_nn + weights
// ===========================================================================
__global__ __launch_bounds__(256)
void three_nn_kernel(const float* __restrict__ xyz1, const float* __restrict__ xyz2)
{
    __shared__ float sx[MPTS], sy[MPTS], sz[MPTS], ss[MPTS];
    const int b = blockIdx.y;
    const float* x2 = xyz2 + (size_t)b * 3 * MPTS;
    for (int i = threadIdx.x; i < MPTS; i += blockDim.x) {
        float xv = x2[i], yv = x2[MPTS + i], zv = x2[2 * MPTS + i];
        sx[i] = xv; sy[i] = yv; sz[i] = zv;
        ss[i] = xv * xv + yv * yv + zv * zv;
    }
    __syncthreads();

    const int n = blockIdx.x * blockDim.x + threadIdx.x;
    const float* x1 = xyz1 + (size_t)b * 3 * NPTS;
    const float px = x1[n], py = x1[NPTS + n], pz = x1[2 * NPTS + n];
    const float sq1 = px * px + py * py + pz * pz;

    float d0 = 1e30f, d1 = 1e30f, d2 = 1e30f;
    int   i0 = 0, i1 = 0, i2 = 0;

    #pragma unroll 4
    for (int m = 0; m < MPTS; m++) {
        float inner = fmaf(px, sx[m], fmaf(py, sy[m], pz * sz[m]));
        float d = fmaf(-2.0f, inner, sq1 + ss[m]);
        if (d < d2) {
            if (d < d1) {
                d2 = d1; i2 = i1;
                if (d < d0) { d1 = d0; i1 = i0; d0 = d; i0 = m; }
                else        { d1 = d;  i1 = m; }
            } else { d2 = d; i2 = m; }
        }
    }

    float r0 = 1.0f / fmaxf(sqrtf(fmaxf(d0, 1e-20f)), 1e-10f);
    float r1 = 1.0f / fmaxf(sqrtf(fmaxf(d1, 1e-20f)), 1e-10f);
    float r2 = 1.0f / fmaxf(sqrtf(fmaxf(d2, 1e-20f)), 1e-10f);
    float inv = 1.0f / (r0 + r1 + r2);

    const int base = (b * NPTS + n) * 3;
    g_idx[base + 0] = i0; g_idx[base + 1] = i1; g_idx[base + 2] = i2;
    g_wgt[base + 0] = r0 * inv; g_wgt[base + 1] = r1 * inv; g_wgt[base + 2] = r2 * inv;
}

// ===========================================================================
// tf32 mma.sync GEMM. 128-thr CTA (4 warps 2x2), CTA tile 128x128,
// warp tile 64x64, BK=16, cp.async double buffer.
// A operands pre-converted (no CVT); B converted post-LDS unless CVT_B==0.
//   MODE 0: Tt  = (W1c[:, :256] @ points2)^T                -> g_Tt [m][o]  (B cvt)
//   MODE 1: y1  = tf32(relu(W1c[:,256:]@points1+b1+gather)) -> g_y1        (B cvt)
//   MODE 2: out = relu(W2c @ y1 + b2)                       -> d_out       (B raw tf32)
// ===========================================================================
#define BK     16
#define ASTR   20    // frag bank = (20g+tc)%32 = 4g+tc + const, bijective
#define BSTR   136   // (128+8): frag bank = (8(tc+ni)+g)%32 bijective

template <int MODE>
__global__ __launch_bounds__(128, 2)
void gemm_mma(const float* __restrict__ X,
              const float* __restrict__ bias,
              float*       __restrict__ Cext)
{
    constexpr int K    = (MODE == 1) ? 128 : 256;
    constexpr int NC   = K / BK;
    constexpr int LDA  = (MODE == 2) ? 256 : LDA_W1;
    constexpr int COFF = (MODE == 1) ? 256 : 0;
    constexpr int LDX  = (MODE == 0) ? MPTS : NPTS;
    constexpr int XBS  = (MODE == 0) ? CH2 * MPTS : (MODE == 1) ? CH1 * NPTS : OUT1 * NPTS;
    constexpr bool CVT_B = (MODE != 2);

    const float* A = (MODE == 2) ? g_W2c : g_W1c;

    __shared__ float As[2][128][ASTR];   // 20.0 KB
    __shared__ float Bs[2][BK][BSTR];    // 17.4 KB

    const int b     = blockIdx.z;
    const int nBase = blockIdx.x * 128;
    const int oBase = blockIdx.y * 128;
    const int tid   = threadIdx.x;
    const int wid   = tid >> 5;
    const int lane  = tid & 31;
    const int g     = lane >> 2;   // 0..7
    const int tc    = lane & 3;    // 0..3

    const int oW = (wid >> 1) * 64;   // 0 or 64
    const int nW = (wid & 1) * 64;    // 0 or 64

    const float* Xb = (MODE == 2) ? (g_y1 + (size_t)b * XBS) : (X + (size_t)b * XBS);

    // A tile 128 x 16 = 512 float4, 4 per thread (rows arow0 + {0,32,64,96})
    const int arow0 = tid >> 2;          // 0..31
    const int ac4   = (tid & 3) * 4;     // 0,4,8,12
    // B tile 16 x 128 = 512 float4, 4 per thread (rows bkr0 + {0,4,8,12})
    const int bkr0  = tid >> 5;          // 0..3
    const int bc4   = (tid & 31) * 4;    // 0..124

    auto prefetch = [&](int c) {
        const int buf = c & 1;
        const int k0  = c * BK;
        const float* ap = &A[(size_t)(oBase + arow0) * LDA + COFF + k0 + ac4];
        cp16(&As[buf][arow0     ][ac4], ap);
        cp16(&As[buf][arow0 + 32][ac4], ap + (size_t)32 * LDA);
        cp16(&As[buf][arow0 + 64][ac4], ap + (size_t)64 * LDA);
        cp16(&As[buf][arow0 + 96][ac4], ap + (size_t)96 * LDA);
        const float* bp = &Xb[(size_t)(k0 + bkr0) * LDX + nBase + bc4];
        cp16(&Bs[buf][bkr0     ][bc4], bp);
        cp16(&Bs[buf][bkr0 +  4][bc4], bp + (size_t)4  * LDX);
        cp16(&Bs[buf][bkr0 +  8][bc4], bp + (size_t)8  * LDX);
        cp16(&Bs[buf][bkr0 + 12][bc4], bp + (size_t)12 * LDX);
        asm volatile("cp.async.commit_group;" ::: "memory");
    };

    float c[4][8][4];   // [mi][ni][reg]  128 regs
    #pragma unroll
    for (int mi = 0; mi < 4; mi++)
        #pragma unroll
        for (int ni = 0; ni < 8; ni++)
            #pragma unroll
            for (int q = 0; q < 4; q++) c[mi][ni][q] = 0.0f;

    prefetch(0);
    asm volatile("cp.async.wait_group 0;" ::: "memory");
    __syncthreads();

    for (int cc = 0; cc < NC; cc++) {
        const int cur = cc & 1;
        if (cc + 1 < NC) prefetch(cc + 1);

        #pragma unroll
        for (int kk = 0; kk < BK; kk += 8) {
            uint32_t a[4][4];
            #pragma unroll
            for (int mi = 0; mi < 4; mi++) {
                int rb = oW + mi * 16;
                a[mi][0] = __float_as_uint(As[cur][rb + g    ][kk + tc    ]);
                a[mi][1] = __float_as_uint(As[cur][rb + g + 8][kk + tc    ]);
                a[mi][2] = __float_as_uint(As[cur][rb + g    ][kk + tc + 4]);
                a[mi][3] = __float_as_uint(As[cur][rb + g + 8][kk + tc + 4]);
            }
            uint32_t bb[8][2];
            #pragma unroll
            for (int ni = 0; ni < 8; ni++) {
                int nb = nW + ni * 8 + g;
                if (CVT_B) {
                    bb[ni][0] = f2tf32(Bs[cur][kk + tc    ][nb]);
                    bb[ni][1] = f2tf32(Bs[cur][kk + tc + 4][nb]);
                } else {
                    bb[ni][0] = __float_as_uint(Bs[cur][kk + tc    ][nb]);
                    bb[ni][1] = __float_as_uint(Bs[cur][kk + tc + 4][nb]);
                }
            }
            #pragma unroll
            for (int mi = 0; mi < 4; mi++)
                #pragma unroll
                for (int ni = 0; ni < 8; ni++) {
                    asm volatile(
                        "mma.sync.aligned.m16n8k8.row.col.f32.tf32.tf32.f32 "
                        "{%0,%1,%2,%3}, {%4,%5,%6,%7}, {%8,%9}, {%0,%1,%2,%3};"
                        : "+f"(c[mi][ni][0]), "+f"(c[mi][ni][1]),
                          "+f"(c[mi][ni][2]), "+f"(c[mi][ni][3])
                        : "r"(a[mi][0]), "r"(a[mi][1]), "r"(a[mi][2]), "r"(a[mi][3]),
                          "r"(bb[ni][0]), "r"(bb[ni][1]));
                }
        }

        asm volatile("cp.async.wait_group 0;" ::: "memory");
        __syncthreads();
    }

    // ---- epilogue ----
    // element (mi, ni, q): o = oBase+oW+mi*16+g+(q>=2)*8 ; n = nBase+nW+ni*8+tc*2+(q&1)

    if (MODE == 0) {
        // store transposed: Tt[m][o], o contiguous, fp32
        float* Cb = g_Tt + (size_t)b * MPTS * OUT1;
        #pragma unroll
        for (int ni = 0; ni < 8; ni++) {
            #pragma unroll
            for (int t = 0; t < 2; t++) {
                int m = nBase + nW + ni * 8 + tc * 2 + t;
                float* mrow = Cb + (size_t)m * OUT1;
                #pragma unroll
                for (int mi = 0; mi < 4; mi++) {
                    #pragma unroll
                    for (int h = 0; h < 2; h++) {
                        int o = oBase + oW + mi * 16 + g + h * 8;
                        mrow[o] = c[mi][ni][h * 2 + t];
                    }
                }
            }
        }
        return;
    }

    constexpr int LDC = NPTS;
    float* Cb = (MODE == 1) ? (g_y1 + (size_t)b * OUT1 * NPTS)
                            : (Cext + (size_t)b * OUT1 * NPTS);

    if (MODE == 1) {
        // gather from transposed T: rows contiguous in o
        const float* Tb = g_Tt + (size_t)b * MPTS * OUT1;
        const int*   ib = g_idx + (size_t)b * NPTS * 3;
        const float* wb = g_wgt + (size_t)b * NPTS * 3;
        #pragma unroll
        for (int ni = 0; ni < 8; ni++) {
            #pragma unroll
            for (int t = 0; t < 2; t++) {
                int n  = nBase + nW + ni * 8 + tc * 2 + t;
                int j0 = ib[n * 3 + 0], j1 = ib[n * 3 + 1], j2 = ib[n * 3 + 2];
                float w0 = wb[n * 3 + 0], w1 = wb[n * 3 + 1], w2 = wb[n * 3 + 2];
                const float* r0 = Tb + (size_t)j0 * OUT1;
                const float* r1 = Tb + (size_t)j1 * OUT1;
                const float* r2 = Tb + (size_t)j2 * OUT1;
                #pragma unroll
                for (int mi = 0; mi < 4; mi++) {
                    #pragma unroll
                    for (int h = 0; h < 2; h++) {
                        int o = oBase + oW + mi * 16 + g + h * 8;
                        c[mi][ni][h * 2 + t] +=
                            w0 * __ldg(&r0[o]) + w1 * __ldg(&r1[o]) + w2 * __ldg(&r2[o]);
                    }
                }
            }
        }
    }

    #pragma unroll
    for (int mi = 0; mi < 4; mi++) {
        #pragma unroll
        for (int h = 0; h < 2; h++) {
            int o = oBase + oW + mi * 16 + g + h * 8;
            float bv = bias[o];
            float* orow = Cb + (size_t)o * LDC;
            #pragma unroll
            for (int ni = 0; ni < 8; ni++) {
                int n = nBase + nW + ni * 8 + tc * 2;
                float v0 = fmaxf(c[mi][ni][h * 2 + 0] + bv, 0.0f);
                float v1 = fmaxf(c[mi][ni][h * 2 + 1] + bv, 0.0f);
                if (MODE == 1) {
                    // store as tf32 bit patterns (consumed raw by gemm2)
                    v0 = __uint_as_float(f2tf32(v0));
                    v1 = __uint_as_float(f2tf32(v1));
                }
                *reinterpret_cast<float2*>(&orow[n]) = make_float2(v0, v1);
            }
        }
    }
}

// ===========================================================================
extern "C" void kernel_launch(void* const* d_in, const int* in_sizes, int n_in,
                              void* d_out, int out_size)
{
    const float* xyz1    = (const float*)d_in[0];
    const float* xyz2    = (const float*)d_in[1];
    const float* points1 = (const float*)d_in[2];
    const float* points2 = (const float*)d_in[3];
    const float* W1      = (const float*)d_in[4];
    const float* b1      = (const float*)d_in[5];
    const float* W2      = (const float*)d_in[6];
    const float* b2      = (const float*)d_in[7];
    float*       out     = (float*)d_out;

    conv_w_kernel<<<(OUT1 * LDA_W1 + 255) / 256, 256>>>(W1, W2);

    three_nn_kernel<<<dim3(NPTS / 256, NB), 256>>>(xyz1, xyz2);

    // Tt = (W1[:, :256] @ points2)^T
    gemm_mma<0><<<dim3(MPTS / 128, OUT1 / 128, NB), 128>>>(points2, nullptr, nullptr);

    // y1 = tf32(relu(W1[:, 256:] @ points1 + b1 + gathered Tt))
    gemm_mma<1><<<dim3(NPTS / 128, OUT1 / 128, NB), 128>>>(points1, b1, nullptr);

    // out = relu(W2 @ y1 + b2)
    gemm_mma<2><<<dim3(NPTS / 128, OUT2 / 128, NB), 128>>>(nullptr, b2, out);
}

// round 9
// speedup vs baseline: 1.2218x; 1.2218x over previous
#include <cuda_runtime.h>
#include <cuda_fp16.h>
#include <math.h>
#include <cstdint>

// Problem constants
#define NB    16
#define NPTS  4096
#define MPTS  1024
#define CH2   256
#define CH1   128
#define OUT1  256
#define OUT2  256
#define LDA_W1 384

// ---- scratch ----
__device__ int    g_idx[NB * NPTS * 3];
__device__ float  g_wgt[NB * NPTS * 3];
__device__ float  g_Tt [NB * MPTS * OUT1];    // T transposed [b][m][o], fp32 (gather src)
__device__ __half g_y1h[NB * OUT1 * NPTS];    // layer-1 activations, half
__device__ __half g_W1h[OUT1 * LDA_W1];
__device__ __half g_W2h[OUT2 * OUT1];
__device__ __half g_p1h[NB * CH1 * NPTS];
__device__ __half g_p2h[NB * CH2 * MPTS];

// ===========================================================================
__device__ __forceinline__ uint32_t smem_u32(const void* p) {
    uint32_t a;
    asm("{ .reg .u64 t; cvta.to.shared.u64 t, %1; cvt.u32.u64 %0, t; }" : "=r"(a) : "l"(p));
    return a;
}
__device__ __forceinline__ void cp16(void* dst, const void* src) {
    asm volatile("cp.async.ca.shared.global [%0], [%1], 16;"
                 :: "r"(smem_u32(dst)), "l"(src));
}
__device__ __forceinline__ void ldsm_x4(uint32_t addr, uint32_t& r0, uint32_t& r1,
                                        uint32_t& r2, uint32_t& r3) {
    asm volatile("ldmatrix.sync.aligned.m8n8.x4.shared.b16 {%0,%1,%2,%3}, [%4];"
                 : "=r"(r0), "=r"(r1), "=r"(r2), "=r"(r3) : "r"(addr));
}
__device__ __forceinline__ void ldsm_x4t(uint32_t addr, uint32_t& r0, uint32_t& r1,
                                         uint32_t& r2, uint32_t& r3) {
    asm volatile("ldmatrix.sync.aligned.m8n8.x4.trans.shared.b16 {%0,%1,%2,%3}, [%4];"
                 : "=r"(r0), "=r"(r1), "=r"(r2), "=r"(r3) : "r"(addr));
}

// ===========================================================================
// Kernel 0: convert weights + activations fp32 -> fp16 (rne)
// ===========================================================================
__global__ __launch_bounds__(256)
void conv_half_kernel(const float* __restrict__ W1, const float* __restrict__ W2,
                      const float* __restrict__ p1, const float* __restrict__ p2)
{
    const int idx0   = blockIdx.x * blockDim.x + threadIdx.x;
    const int stride = gridDim.x * blockDim.x;

    auto conv = [&](const float* __restrict__ src, __half* __restrict__ dst, int n4) {
        for (int i = idx0; i < n4; i += stride) {
            float4 v = reinterpret_cast<const float4*>(src)[i];
            __half2 h0 = __floats2half2_rn(v.x, v.y);
            __half2 h1 = __floats2half2_rn(v.z, v.w);
            reinterpret_cast<__half2*>(dst)[2 * i + 0] = h0;
            reinterpret_cast<__half2*>(dst)[2 * i + 1] = h1;
        }
    };
    conv(W1, g_W1h, OUT1 * LDA_W1 / 4);
    conv(W2, g_W2h, OUT2 * OUT1 / 4);
    conv(p1, g_p1h, NB * CH1 * NPTS / 4);
    conv(p2, g_p2h, NB * CH2 * MPTS / 4);
}

// ===========================================================================
// Kernel 1: three_nn + weights
// ===========================================================================
__global__ __launch_bounds__(256)
void three_nn_kernel(const float* __restrict__ xyz1, const float* __restrict__ xyz2)
{
    __shared__ float sx[MPTS], sy[MPTS], sz[MPTS], ss[MPTS];
    const int b = blockIdx.y;
    const float* x2 = xyz2 + (size_t)b * 3 * MPTS;
    for (int i = threadIdx.x; i < MPTS; i += blockDim.x) {
        float xv = x2[i], yv = x2[MPTS + i], zv = x2[2 * MPTS + i];
        sx[i] = xv; sy[i] = yv; sz[i] = zv;
        ss[i] = xv * xv + yv * yv + zv * zv;
    }
    __syncthreads();

    const int n = blockIdx.x * blockDim.x + threadIdx.x;
    const float* x1 = xyz1 + (size_t)b * 3 * NPTS;
    const float px = x1[n], py = x1[NPTS + n], pz = x1[2 * NPTS + n];
    const float sq1 = px * px + py * py + pz * pz;

    float d0 = 1e30f, d1 = 1e30f, d2 = 1e30f;
    int   i0 = 0, i1 = 0, i2 = 0;

    #pragma unroll 4
    for (int m = 0; m < MPTS; m++) {
        float inner = fmaf(px, sx[m], fmaf(py, sy[m], pz * sz[m]));
        float d = fmaf(-2.0f, inner, sq1 + ss[m]);
        if (d < d2) {
            if (d < d1) {
                d2 = d1; i2 = i1;
                if (d < d0) { d1 = d0; i1 = i0; d0 = d; i0 = m; }
                else        { d1 = d;  i1 = m; }
            } else { d2 = d; i2 = m; }
        }
    }

    float r0 = 1.0f / fmaxf(sqrtf(fmaxf(d0, 1e-20f)), 1e-10f);
    float r1 = 1.0f / fmaxf(sqrtf(fmaxf(d1, 1e-20f)), 1e-10f);
    float r2 = 1.0f / fmaxf(sqrtf(fmaxf(d2, 1e-20f)), 1e-10f);
    float inv = 1.0f / (r0 + r1 + r2);

    const int base = (b * NPTS + n) * 3;
    g_idx[base + 0] = i0; g_idx[base + 1] = i1; g_idx[base + 2] = i2;
    g_wgt[base + 0] = r0 * inv; g_wgt[base + 1] = r1 * inv; g_wgt[base + 2] = r2 * inv;
}

// ===========================================================================
// fp16 mma.sync (m16n8k16) GEMM with ldmatrix + cp.async double buffer.
// 256-thr CTA, 8 warps (2x4), CTA tile 128x128, warp tile 64x32, BK=32.
//   MODE 0: Tt  = (W1h[:, :256] @ p2h)^T                  -> g_Tt [m][o] f32
//   MODE 1: y1h = h(relu(W1h[:,256:]@p1h + b1 + gather))  -> g_y1h
//   MODE 2: out = relu(W2h @ y1h + b2)                    -> d_out f32
// ===========================================================================
#define BK    32
#define ASTR  40     // halves per As row (32 + 8 pad) — LDSM phases partition banks
#define BSTR  136    // halves per Bs row (128 + 8 pad)

template <int MODE>
__global__ __launch_bounds__(256, 2)
void gemm_mma(const float* __restrict__ bias, float* __restrict__ Cext)
{
    constexpr int K    = (MODE == 1) ? 128 : 256;
    constexpr int NC   = K / BK;
    constexpr int LDA  = (MODE == 2) ? 256 : LDA_W1;
    constexpr int COFF = (MODE == 1) ? 256 : 0;
    constexpr int LDX  = (MODE == 0) ? MPTS : NPTS;
    constexpr int XBS  = (MODE == 0) ? CH2 * MPTS : (MODE == 1) ? CH1 * NPTS : OUT1 * NPTS;

    const __half* Ah = (MODE == 2) ? g_W2h : g_W1h;
    const __half* Xh = (MODE == 0) ? g_p2h : (MODE == 1) ? g_p1h : g_y1h;

    __shared__ __align__(16) __half As[2][128][ASTR];   // 20.0 KB
    __shared__ __align__(16) __half Bs[2][BK][BSTR];    // 17.4 KB

    const int b     = blockIdx.z;
    const int nBase = blockIdx.x * 128;
    const int oBase = blockIdx.y * 128;
    const int tid   = threadIdx.x;
    const int wid   = tid >> 5;
    const int lane  = tid & 31;
    const int g     = lane >> 2;   // 0..7
    const int tc    = lane & 3;    // 0..3

    const int oW = (wid >> 2) * 64;   // 0 or 64
    const int nW = (wid & 3) * 32;    // 0,32,64,96

    const __half* Xb = Xh + (size_t)b * XBS;

    // cp.async task mapping
    const int arow = tid & 127;          // A row
    const int akc0 = tid >> 7;           // A 8-half group (and +2)
    const int bk0  = tid >> 4;           // B k row for l=0 (lin>>4), +16 for l=1
    const int bn8  = tid & 15;           // B 8-half n group

    auto prefetch = [&](int c) {
        const int buf = c & 1;
        const int k0  = c * BK;
        const __half* ap = &Ah[(size_t)(oBase + arow) * LDA + COFF + k0];
        cp16(&As[buf][arow][8 * akc0],       ap + 8 * akc0);
        cp16(&As[buf][arow][8 * (akc0 + 2)], ap + 8 * (akc0 + 2));
        const __half* bp = &Xb[(size_t)k0 * LDX + nBase + 8 * bn8];
        cp16(&Bs[buf][bk0     ][8 * bn8], bp + (size_t)bk0 * LDX);
        cp16(&Bs[buf][bk0 + 16][8 * bn8], bp + (size_t)(bk0 + 16) * LDX);
        asm volatile("cp.async.commit_group;" ::: "memory");
    };

    // ldmatrix per-lane address offsets (bytes)
    const int lm = lane >> 3;   // matrix index 0..3
    const int lr = lane & 7;    // row within matrix
    uint32_t aoff[4];
    #pragma unroll
    for (int mi = 0; mi < 4; mi++)
        aoff[mi] = ((oW + mi * 16 + lr + 8 * (lm & 1)) * ASTR + 8 * (lm >> 1)) * 2;
    uint32_t boff[2];
    #pragma unroll
    for (int pr = 0; pr < 2; pr++)
        boff[pr] = ((lr + 8 * (lm & 1)) * BSTR + nW + pr * 16 + 8 * (lm >> 1)) * 2;

    const uint32_t as_base = smem_u32(&As[0][0][0]);
    const uint32_t bs_base = smem_u32(&Bs[0][0][0]);
    constexpr uint32_t AS_BUF = 128 * ASTR * 2;
    constexpr uint32_t BS_BUF = BK * BSTR * 2;

    float c[4][4][4];
    #pragma unroll
    for (int mi = 0; mi < 4; mi++)
        #pragma unroll
        for (int ni = 0; ni < 4; ni++)
            #pragma unroll
            for (int q = 0; q < 4; q++) c[mi][ni][q] = 0.0f;

    prefetch(0);
    asm volatile("cp.async.wait_group 0;" ::: "memory");
    __syncthreads();

    for (int cc = 0; cc < NC; cc++) {
        const uint32_t asb = as_base + (cc & 1) * AS_BUF;
        const uint32_t bsb = bs_base + (cc & 1) * BS_BUF;
        if (cc + 1 < NC) prefetch(cc + 1);

        #pragma unroll
        for (int kk = 0; kk < BK; kk += 16) {
            uint32_t a[4][4];
            #pragma unroll
            for (int mi = 0; mi < 4; mi++)
                ldsm_x4(asb + aoff[mi] + kk * 2, a[mi][0], a[mi][1], a[mi][2], a[mi][3]);
            uint32_t bb[4][2];
            ldsm_x4t(bsb + boff[0] + kk * (BSTR * 2), bb[0][0], bb[0][1], bb[1][0], bb[1][1]);
            ldsm_x4t(bsb + boff[1] + kk * (BSTR * 2), bb[2][0], bb[2][1], bb[3][0], bb[3][1]);
            #pragma unroll
            for (int mi = 0; mi < 4; mi++)
                #pragma unroll
                for (int ni = 0; ni < 4; ni++) {
                    asm volatile(
                        "mma.sync.aligned.m16n8k16.row.col.f32.f16.f16.f32 "
                        "{%0,%1,%2,%3}, {%4,%5,%6,%7}, {%8,%9}, {%0,%1,%2,%3};"
                        : "+f"(c[mi][ni][0]), "+f"(c[mi][ni][1]),
                          "+f"(c[mi][ni][2]), "+f"(c[mi][ni][3])
                        : "r"(a[mi][0]), "r"(a[mi][1]), "r"(a[mi][2]), "r"(a[mi][3]),
                          "r"(bb[ni][0]), "r"(bb[ni][1]));
                }
        }

        asm volatile("cp.async.wait_group 0;" ::: "memory");
        __syncthreads();
    }

    // ---- epilogue ----
    // element (mi, ni, q): o = oBase+oW+mi*16+g+(q>=2)*8 ; n = nBase+nW+ni*8+tc*2+(q&1)

    if (MODE == 0) {
        float* Cb = g_Tt + (size_t)b * MPTS * OUT1;
        #pragma unroll
        for (int ni = 0; ni < 4; ni++) {
            #pragma unroll
            for (int t = 0; t < 2; t++) {
                int m = nBase + nW + ni * 8 + tc * 2 + t;
                float* mrow = Cb + (size_t)m * OUT1;
                #pragma unroll
                for (int mi = 0; mi < 4; mi++) {
                    #pragma unroll
                    for (int h = 0; h < 2; h++) {
                        int o = oBase + oW + mi * 16 + g + h * 8;
                        mrow[o] = c[mi][ni][h * 2 + t];
                    }
                }
            }
        }
        return;
    }

    if (MODE == 1) {
        const float* Tb = g_Tt + (size_t)b * MPTS * OUT1;
        const int*   ib = g_idx + (size_t)b * NPTS * 3;
        const float* wb = g_wgt + (size_t)b * NPTS * 3;
        #pragma unroll
        for (int ni = 0; ni < 4; ni++) {
            #pragma unroll
            for (int t = 0; t < 2; t++) {
                int n  = nBase + nW + ni * 8 + tc * 2 + t;
                int j0 = ib[n * 3 + 0], j1 = ib[n * 3 + 1], j2 = ib[n * 3 + 2];
                float w0 = wb[n * 3 + 0], w1 = wb[n * 3 + 1], w2 = wb[n * 3 + 2];
                const float* r0 = Tb + (size_t)j0 * OUT1;
                const float* r1 = Tb + (size_t)j1 * OUT1;
                const float* r2 = Tb + (size_t)j2 * OUT1;
                #pragma unroll
                for (int mi = 0; mi < 4; mi++) {
                    #pragma unroll
                    for (int h = 0; h < 2; h++) {
                        int o = oBase + oW + mi * 16 + g + h * 8;
                        c[mi][ni][h * 2 + t] +=
                            w0 * __ldg(&r0[o]) + w1 * __ldg(&r1[o]) + w2 * __ldg(&r2[o]);
                    }
                }
            }
        }
        // bias + relu + half store
        __half* Cb = g_y1h + (size_t)b * OUT1 * NPTS;
        #pragma unroll
        for (int mi = 0; mi < 4; mi++) {
            #pragma unroll
            for (int h = 0; h < 2; h++) {
                int o = oBase + oW + mi * 16 + g + h * 8;
                float bv = bias[o];
                __half* orow = Cb + (size_t)o * NPTS;
                #pragma unroll
                for (int ni = 0; ni < 4; ni++) {
                    int n = nBase + nW + ni * 8 + tc * 2;
                    float v0 = fmaxf(c[mi][ni][h * 2 + 0] + bv, 0.0f);
                    float v1 = fmaxf(c[mi][ni][h * 2 + 1] + bv, 0.0f);
                    *reinterpret_cast<__half2*>(&orow[n]) = __floats2half2_rn(v0, v1);
                }
            }
        }
        return;
    }

    // MODE 2: final output fp32
    float* Cb = Cext + (size_t)b * OUT2 * NPTS;
    #pragma unroll
    for (int mi = 0; mi < 4; mi++) {
        #pragma unroll
        for (int h = 0; h < 2; h++) {
            int o = oBase + oW + mi * 16 + g + h * 8;
            float bv = bias[o];
            float* orow = Cb + (size_t)o * NPTS;
            #pragma unroll
            for (int ni = 0; ni < 4; ni++) {
                int n = nBase + nW + ni * 8 + tc * 2;
                float v0 = fmaxf(c[mi][ni][h * 2 + 0] + bv, 0.0f);
                float v1 = fmaxf(c[mi][ni][h * 2 + 1] + bv, 0.0f);
                *reinterpret_cast<float2*>(&orow[n]) = make_float2(v0, v1);
            }
        }
    }
}

// ===========================================================================
extern "C" void kernel_launch(void* const* d_in, const int* in_sizes, int n_in,
                              void* d_out, int out_size)
{
    const float* xyz1    = (const float*)d_in[0];
    const float* xyz2    = (const float*)d_in[1];
    const float* points1 = (const float*)d_in[2];
    const float* points2 = (const float*)d_in[3];
    const float* W1      = (const float*)d_in[4];
    const float* b1      = (const float*)d_in[5];
    const float* W2      = (const float*)d_in[6];
    const float* b2      = (const float*)d_in[7];
    float*       out     = (float*)d_out;

    conv_half_kernel<<<1024, 256>>>(W1, W2, points1, points2);

    three_nn_kernel<<<dim3(NPTS / 256, NB), 256>>>(xyz1, xyz2);

    // Tt = (W1[:, :256] @ points2)^T
    gemm_mma<0><<<dim3(MPTS / 128, OUT1 / 128, NB), 256>>>(nullptr, nullptr);

    // y1h = half(relu(W1[:, 256:] @ points1 + b1 + gathered Tt))
    gemm_mma<1><<<dim3(NPTS / 128, OUT1 / 128, NB), 256>>>(b1, nullptr);

    // out = relu(W2 @ y1h + b2)
    gemm_mma<2><<<dim3(NPTS / 128, OUT2 / 128, NB), 256>>>(b2, out);
}